// round 1
// baseline (speedup 1.0000x reference)
#include <cuda_runtime.h>
#include <cstdint>
#include <cstddef>

// ---------------- problem constants ----------------
#define NB   8192   // batch
#define NTT  100    // encoder time steps
#define NIN  16     // encoder input dim
#define NH   128    // hidden
#define NG   512    // 4*H gate rows
#define NOUT 2      // fc output dim

#define MT   64     // batch rows per CTA
#define NTHR 512    // threads per CTA
#define APAD 68     // padded row stride for [k][row] activation buffers
#define CSTR 130    // row stride for [row][j] cell-state buffers

// ---------------- packed weight scratch (k-major [K][512]) ----------------
#define OFS_EWIH0 0
#define OFS_EWHH0 (OFS_EWIH0 + 16*NG)
#define OFS_EWIH1 (OFS_EWHH0 + NH*NG)
#define OFS_EWHH1 (OFS_EWIH1 + NH*NG)
#define OFS_DWIH0 (OFS_EWHH1 + NH*NG)
#define OFS_DWHH0 (OFS_DWIH0 + 2*NG)
#define OFS_DWIH1 (OFS_DWHH0 + NH*NG)
#define OFS_DWHH1 (OFS_DWIH1 + NH*NG)
#define OFS_BE0   (OFS_DWHH1 + NH*NG)
#define OFS_BE1   (OFS_BE0 + NG)
#define OFS_BD0   (OFS_BE1 + NG)
#define OFS_BD1   (OFS_BD0 + NG)
#define PACK_TOTAL (OFS_BD1 + NG)

__device__ float g_pack[PACK_TOTAL];

// ---------------- shared memory layout (floats) ----------------
#define SH_H0  0
#define SH_H1  (SH_H0 + NH*APAD)
#define SH_C0  (SH_H1 + NH*APAD)
#define SH_C1  (SH_C0 + MT*CSTR)
#define SH_X   (SH_C1 + MT*CSTR)          // [16][APAD], also decoder input [2][APAD]
#define SH_WB  (SH_X + NIN*APAD)          // 2 x (16x512) weight tile double buffer
#define SH_BE0 (SH_WB + 2*16*NG)
#define SH_BE1 (SH_BE0 + NG)
#define SH_BD0 (SH_BE1 + NG)
#define SH_BD1 (SH_BD0 + NG)
#define SH_DW0 (SH_BD1 + NG)              // dW_ih0 packed [2][512]
#define SH_FCW (SH_DW0 + 2*NG)            // [2][128]
#define SH_FCB (SH_FCW + NOUT*NH)
#define SH_TOTAL (SH_FCB + 8)
#define SH_BYTES (SH_TOTAL * 4)

// ---------------- cp.async helpers ----------------
__device__ __forceinline__ void cp16(void* dst, const void* src) {
    unsigned d = (unsigned)__cvta_generic_to_shared(dst);
    asm volatile("cp.async.cg.shared.global [%0], [%1], 16;\n" :: "r"(d), "l"(src) : "memory");
}
__device__ __forceinline__ void cp_commit() { asm volatile("cp.async.commit_group;\n" ::: "memory"); }
__device__ __forceinline__ void cp_wait0()  { asm volatile("cp.async.wait_group 0;\n" ::: "memory"); }
__device__ __forceinline__ void cp_wait1()  { asm volatile("cp.async.wait_group 1;\n" ::: "memory"); }

// stage one 16x512 fp32 tile (32KB) : 512 threads x 4 float4
__device__ __forceinline__ void stage_tile(float* buf, const float* src, int tid) {
    #pragma unroll
    for (int i = 0; i < 4; ++i)
        cp16(buf + (tid + i * NTHR) * 4, src + (tid + i * NTHR) * 4);
}

// ---------------- activations (saturation-safe fast forms) ----------------
__device__ __forceinline__ float sigf(float x)   { return __fdividef(1.f, 1.f + __expf(-x)); }
__device__ __forceinline__ float tanh_f(float x) { return __fdividef(2.f, 1.f + __expf(-2.f * x)) - 1.f; }

// ---------------- GEMM micro-kernels ----------------
// acc[ri][2*g+jj] for rows r0..r0+7, cols g*128 + j0 + jj
__device__ __forceinline__ void mm_tile16(float (&acc)[8][8], const float* __restrict__ wt,
                                          const float* __restrict__ A_s, int r0, int j0)
{
    #pragma unroll 4
    for (int kk = 0; kk < 16; ++kk) {
        const float* ar = A_s + kk * APAD + r0;
        float4 a0 = *(const float4*)(ar);
        float4 a1 = *(const float4*)(ar + 4);
        float a[8] = {a0.x, a0.y, a0.z, a0.w, a1.x, a1.y, a1.z, a1.w};
        #pragma unroll
        for (int g = 0; g < 4; ++g) {
            float2 w = *(const float2*)(wt + kk * NG + g * NH + j0);
            #pragma unroll
            for (int ri = 0; ri < 8; ++ri) {
                acc[ri][2*g+0] = fmaf(a[ri], w.x, acc[ri][2*g+0]);
                acc[ri][2*g+1] = fmaf(a[ri], w.y, acc[ri][2*g+1]);
            }
        }
    }
}

// K=2 phase for decoder layer0 (weights resident in smem)
__device__ __forceinline__ void mm_k2(float (&acc)[8][8], const float* __restrict__ w_s,
                                      const float* __restrict__ in_s, int r0, int j0)
{
    #pragma unroll
    for (int kk = 0; kk < 2; ++kk) {
        const float* ar = in_s + kk * APAD + r0;
        float4 a0 = *(const float4*)(ar);
        float4 a1 = *(const float4*)(ar + 4);
        float a[8] = {a0.x, a0.y, a0.z, a0.w, a1.x, a1.y, a1.z, a1.w};
        #pragma unroll
        for (int g = 0; g < 4; ++g) {
            float2 w = *(const float2*)(w_s + kk * NG + g * NH + j0);
            #pragma unroll
            for (int ri = 0; ri < 8; ++ri) {
                acc[ri][2*g+0] = fmaf(a[ri], w.x, acc[ri][2*g+0]);
                acc[ri][2*g+1] = fmaf(a[ri], w.y, acc[ri][2*g+1]);
            }
        }
    }
}

// One GEMM phase: stream packed W [nk][512] in 16-row tiles, double-buffered cp.async
__device__ __forceinline__ void gemm_phase(float (&acc)[8][8], const float* __restrict__ Wg,
                                           int nk, const float* __restrict__ A_s,
                                           float* __restrict__ wb, int tid, int r0, int j0)
{
    const int nt = nk >> 4;
    stage_tile(wb, Wg, tid); cp_commit();
    if (nt > 1) { stage_tile(wb + 16*NG, Wg + 16*NG, tid); cp_commit(); }
    #pragma unroll 1
    for (int it = 0; it < nt; ++it) {
        if (it + 1 < nt) cp_wait1(); else cp_wait0();
        __syncthreads();
        mm_tile16(acc, wb + (it & 1) * 16*NG, A_s + it * 16 * APAD, r0, j0);
        __syncthreads();
        if (it + 2 < nt) { stage_tile(wb + (it & 1) * 16*NG, Wg + (it + 2) * 16*NG, tid); cp_commit(); }
    }
}

__device__ __forceinline__ void init_acc(float (&acc)[8][8], const float* __restrict__ bias_s, int j0) {
    #pragma unroll
    for (int g = 0; g < 4; ++g)
        #pragma unroll
        for (int jj = 0; jj < 2; ++jj) {
            float b = bias_s[g * NH + j0 + jj];
            #pragma unroll
            for (int ri = 0; ri < 8; ++ri) acc[ri][2*g+jj] = b;
        }
}

// sigmoid/tanh gating, c update (smem [row][j]), new h -> smem [j][row]
__device__ __forceinline__ void cell_update(float (&acc)[8][8], float* __restrict__ c_s,
                                            float* __restrict__ h_s, int r0, int j0)
{
    #pragma unroll
    for (int jj = 0; jj < 2; ++jj) {
        int j = j0 + jj;
        float hv[8];
        #pragma unroll
        for (int ri = 0; ri < 8; ++ri) {
            float iv = sigf(acc[ri][0+jj]);
            float fv = sigf(acc[ri][2+jj]);
            float gv = tanh_f(acc[ri][4+jj]);
            float ov = sigf(acc[ri][6+jj]);
            float* cp = c_s + (r0 + ri) * CSTR + j;
            float c = fmaf(fv, *cp, iv * gv);
            *cp = c;
            hv[ri] = ov * tanh_f(c);
        }
        *(float4*)(h_s + j * APAD + r0)     = make_float4(hv[0], hv[1], hv[2], hv[3]);
        *(float4*)(h_s + j * APAD + r0 + 4) = make_float4(hv[4], hv[5], hv[6], hv[7]);
    }
    __syncthreads();
}

// ---------------- weight repack kernel: row-major (512,K) -> k-major [K][512]; bias sums ----------------
__global__ void pack_kernel(const float* eW_ih0, const float* eW_hh0,
                            const float* eb_ih0, const float* eb_hh0,
                            const float* eW_ih1, const float* eW_hh1,
                            const float* eb_ih1, const float* eb_hh1,
                            const float* dW_ih0, const float* dW_hh0,
                            const float* db_ih0, const float* db_hh0,
                            const float* dW_ih1, const float* dW_hh1,
                            const float* db_ih1, const float* db_hh1)
{
    int bid = blockIdx.x, tid = threadIdx.x;
    const float* src = nullptr; float* dst = nullptr; int K = 0;
    switch (bid) {
        case 0:  src = eW_ih0; dst = g_pack + OFS_EWIH0; K = 16;  break;
        case 1:  src = eW_hh0; dst = g_pack + OFS_EWHH0; K = 128; break;
        case 2:  src = eW_ih1; dst = g_pack + OFS_EWIH1; K = 128; break;
        case 3:  src = eW_hh1; dst = g_pack + OFS_EWHH1; K = 128; break;
        case 4:  src = dW_ih0; dst = g_pack + OFS_DWIH0; K = 2;   break;
        case 5:  src = dW_hh0; dst = g_pack + OFS_DWHH0; K = 128; break;
        case 6:  src = dW_ih1; dst = g_pack + OFS_DWIH1; K = 128; break;
        case 7:  src = dW_hh1; dst = g_pack + OFS_DWHH1; K = 128; break;
        case 8:  for (int i = tid; i < NG; i += blockDim.x) g_pack[OFS_BE0 + i] = eb_ih0[i] + eb_hh0[i]; return;
        case 9:  for (int i = tid; i < NG; i += blockDim.x) g_pack[OFS_BE1 + i] = eb_ih1[i] + eb_hh1[i]; return;
        case 10: for (int i = tid; i < NG; i += blockDim.x) g_pack[OFS_BD0 + i] = db_ih0[i] + db_hh0[i]; return;
        case 11: for (int i = tid; i < NG; i += blockDim.x) g_pack[OFS_BD1 + i] = db_ih1[i] + db_hh1[i]; return;
        default: return;
    }
    int n = K * NG;
    for (int i = tid; i < n; i += blockDim.x) {
        int k = i / NG, c = i % NG;
        dst[i] = src[c * K + k];    // transpose to k-major
    }
}

// ---------------- fused encoder+decoder persistent kernel ----------------
__global__ void __launch_bounds__(NTHR, 1)
lstm_kernel(const float* __restrict__ x, const int* __restrict__ tlp,
            const float* __restrict__ fcW, const float* __restrict__ fcb,
            float* __restrict__ out)
{
    extern __shared__ float sm[];
    float* h0_s  = sm + SH_H0;
    float* h1_s  = sm + SH_H1;
    float* c0_s  = sm + SH_C0;
    float* c1_s  = sm + SH_C1;
    float* x_s   = sm + SH_X;
    float* wb    = sm + SH_WB;
    float* be0_s = sm + SH_BE0;
    float* be1_s = sm + SH_BE1;
    float* bd0_s = sm + SH_BD0;
    float* bd1_s = sm + SH_BD1;
    float* dw0_s = sm + SH_DW0;
    float* fcw_s = sm + SH_FCW;
    float* fcb_s = sm + SH_FCB;

    const int tid = threadIdx.x;
    const int b0  = blockIdx.x * MT;
    const int r0  = (tid >> 6) * 8;     // 8 batch rows per thread (warp-uniform)
    const int j0  = (tid & 63) * 2;     // 2 adjacent hidden cols per thread

    // preload constants into smem
    for (int i = tid; i < NG; i += NTHR) {
        be0_s[i] = g_pack[OFS_BE0 + i];
        be1_s[i] = g_pack[OFS_BE1 + i];
        bd0_s[i] = g_pack[OFS_BD0 + i];
        bd1_s[i] = g_pack[OFS_BD1 + i];
    }
    for (int i = tid; i < 2 * NG; i += NTHR) dw0_s[i] = g_pack[OFS_DWIH0 + i];
    for (int i = tid; i < NOUT * NH; i += NTHR) fcw_s[i] = fcW[i];
    if (tid < NOUT) fcb_s[tid] = fcb[tid];
    // zero states
    for (int i = tid; i < NH * APAD; i += NTHR) { h0_s[i] = 0.f; h1_s[i] = 0.f; }
    for (int i = tid; i < MT * CSTR; i += NTHR) { c0_s[i] = 0.f; c1_s[i] = 0.f; }
    __syncthreads();

    const int tl = *tlp;
    float acc[8][8];

    // ================= encoder: 100 steps, 2 layers, fused =================
    #pragma unroll 1
    for (int t = 0; t < NTT; ++t) {
        {   // stage x_t transposed into x_s[k][row]
            int r = tid >> 3, i2 = (tid & 7) * 2;
            float2 v = *(const float2*)(x + ((size_t)(b0 + r) * NTT + t) * NIN + i2);
            x_s[i2 * APAD + r]       = v.x;
            x_s[(i2 + 1) * APAD + r] = v.y;
        }
        __syncthreads();
        // layer 0: gates = x @ Wih0^T + h0 @ Whh0^T + b
        init_acc(acc, be0_s, j0);
        gemm_phase(acc, g_pack + OFS_EWIH0, 16,  x_s,  wb, tid, r0, j0);
        gemm_phase(acc, g_pack + OFS_EWHH0, 128, h0_s, wb, tid, r0, j0);
        cell_update(acc, c0_s, h0_s, r0, j0);
        // layer 1: gates = h0_new @ Wih1^T + h1 @ Whh1^T + b
        init_acc(acc, be1_s, j0);
        gemm_phase(acc, g_pack + OFS_EWIH1, 128, h0_s, wb, tid, r0, j0);
        gemm_phase(acc, g_pack + OFS_EWHH1, 128, h1_s, wb, tid, r0, j0);
        cell_update(acc, c1_s, h1_s, r0, j0);
    }

    // decoder initial input: x[:, T-1, 0:2]
    if (tid < 2 * MT) {
        int r = tid >> 1, o = tid & 1;
        x_s[o * APAD + r] = x[((size_t)(b0 + r) * NTT + (NTT - 1)) * NIN + o];
    }
    __syncthreads();

    // ================= decoder: tl steps, 2 layers + fc feedback =================
    #pragma unroll 1
    for (int t = 0; t < tl; ++t) {
        // layer 0: K=2 input phase (smem weights) + recurrent phase
        init_acc(acc, bd0_s, j0);
        mm_k2(acc, dw0_s, x_s, r0, j0);
        gemm_phase(acc, g_pack + OFS_DWHH0, 128, h0_s, wb, tid, r0, j0);
        cell_update(acc, c0_s, h0_s, r0, j0);
        // layer 1
        init_acc(acc, bd1_s, j0);
        gemm_phase(acc, g_pack + OFS_DWIH1, 128, h0_s, wb, tid, r0, j0);
        gemm_phase(acc, g_pack + OFS_DWHH1, 128, h1_s, wb, tid, r0, j0);
        cell_update(acc, c1_s, h1_s, r0, j0);
        // fc: out = h1 @ fcW^T + fcb ; write output + feedback
        if (tid < 2 * MT) {
            int r = tid >> 1, o = tid & 1;
            float s = fcb_s[o];
            #pragma unroll 8
            for (int k = 0; k < NH; ++k)
                s = fmaf(h1_s[k * APAD + r], fcw_s[o * NH + k], s);
            out[((size_t)(b0 + r) * tl + t) * NOUT + o] = s;
            x_s[o * APAD + r] = s;
        }
        __syncthreads();
    }
}

// ---------------- launch ----------------
extern "C" void kernel_launch(void* const* d_in, const int* in_sizes, int n_in,
                              void* d_out, int out_size)
{
    (void)in_sizes; (void)n_in; (void)out_size;
    const float* x      = (const float*)d_in[0];
    const int*   tl     = (const int*)  d_in[1];
    const float* eW_ih0 = (const float*)d_in[2];
    const float* eW_hh0 = (const float*)d_in[3];
    const float* eb_ih0 = (const float*)d_in[4];
    const float* eb_hh0 = (const float*)d_in[5];
    const float* eW_ih1 = (const float*)d_in[6];
    const float* eW_hh1 = (const float*)d_in[7];
    const float* eb_ih1 = (const float*)d_in[8];
    const float* eb_hh1 = (const float*)d_in[9];
    const float* dW_ih0 = (const float*)d_in[10];
    const float* dW_hh0 = (const float*)d_in[11];
    const float* db_ih0 = (const float*)d_in[12];
    const float* db_hh0 = (const float*)d_in[13];
    const float* dW_ih1 = (const float*)d_in[14];
    const float* dW_hh1 = (const float*)d_in[15];
    const float* db_ih1 = (const float*)d_in[16];
    const float* db_hh1 = (const float*)d_in[17];
    const float* fcW    = (const float*)d_in[18];
    const float* fcb    = (const float*)d_in[19];

    cudaFuncSetAttribute(lstm_kernel, cudaFuncAttributeMaxDynamicSharedMemorySize, SH_BYTES);

    pack_kernel<<<12, 256>>>(eW_ih0, eW_hh0, eb_ih0, eb_hh0,
                             eW_ih1, eW_hh1, eb_ih1, eb_hh1,
                             dW_ih0, dW_hh0, db_ih0, db_hh0,
                             dW_ih1, dW_hh1, db_ih1, db_hh1);

    lstm_kernel<<<NB / MT, NTHR, SH_BYTES>>>(x, tl, fcW, fcb, (float*)d_out);
}

// round 2
// speedup vs baseline: 1.0362x; 1.0362x over previous
#include <cuda_runtime.h>
#include <cstdint>
#include <cstddef>

typedef unsigned long long u64;

// ---------------- problem constants ----------------
#define NB   8192   // batch
#define NTT  100    // encoder time steps
#define NIN  16     // encoder input dim
#define NH   128    // hidden
#define NG   512    // 4*H gate rows
#define NOUT 2      // fc output dim

#define MT   64     // batch rows per CTA
#define NTHR 512    // threads per CTA
#define APAD 68     // padded row stride for [k][row] activation buffers
#define CSTR 130    // row stride for [row][j] cell-state buffers

// ---------------- packed f32x2 helpers (Blackwell) ----------------
#define FMA2(d, a, b) asm("fma.rn.f32x2 %0, %1, %2, %0;" : "+l"(d) : "l"(a), "l"(b))
#define PACK2(d, lo, hi) asm("mov.b64 %0, {%1, %2};" : "=l"(d) : "f"(lo), "f"(hi))
#define UNPACK2(lo, hi, v) asm("mov.b64 {%0, %1}, %2;" : "=f"(lo), "=f"(hi) : "l"(v))

// ---------------- packed weight scratch (k-major [K][512]) ----------------
#define OFS_EWIH0 0
#define OFS_EWHH0 (OFS_EWIH0 + 16*NG)
#define OFS_EWIH1 (OFS_EWHH0 + NH*NG)
#define OFS_EWHH1 (OFS_EWIH1 + NH*NG)
#define OFS_DWIH0 (OFS_EWHH1 + NH*NG)
#define OFS_DWHH0 (OFS_DWIH0 + 2*NG)
#define OFS_DWIH1 (OFS_DWHH0 + NH*NG)
#define OFS_DWHH1 (OFS_DWIH1 + NH*NG)
#define OFS_BE0   (OFS_DWHH1 + NH*NG)
#define OFS_BE1   (OFS_BE0 + NG)
#define OFS_BD0   (OFS_BE1 + NG)
#define OFS_BD1   (OFS_BD0 + NG)
#define PACK_TOTAL (OFS_BD1 + NG)

__device__ float g_pack[PACK_TOTAL];

// ---------------- shared memory layout (floats) ----------------
#define SH_H0  0
#define SH_H1  (SH_H0 + NH*APAD)
#define SH_C0  (SH_H1 + NH*APAD)
#define SH_C1  (SH_C0 + MT*CSTR)
#define SH_X   (SH_C1 + MT*CSTR)          // [16][APAD], also decoder input [2][APAD]
#define SH_WB  (SH_X + NIN*APAD)          // 2 x (16x512) weight tile double buffer
#define SH_BE0 (SH_WB + 2*16*NG)
#define SH_BE1 (SH_BE0 + NG)
#define SH_BD0 (SH_BE1 + NG)
#define SH_BD1 (SH_BD0 + NG)
#define SH_DW0 (SH_BD1 + NG)              // dW_ih0 packed [2][512]
#define SH_FCW (SH_DW0 + 2*NG)            // [2][128]
#define SH_FCB (SH_FCW + NOUT*NH)
#define SH_TOTAL (SH_FCB + 8)
#define SH_BYTES (SH_TOTAL * 4)

// ---------------- cp.async helpers ----------------
__device__ __forceinline__ void cp16(void* dst, const void* src) {
    unsigned d = (unsigned)__cvta_generic_to_shared(dst);
    asm volatile("cp.async.cg.shared.global [%0], [%1], 16;\n" :: "r"(d), "l"(src) : "memory");
}
__device__ __forceinline__ void cp_commit() { asm volatile("cp.async.commit_group;\n" ::: "memory"); }
__device__ __forceinline__ void cp_wait0()  { asm volatile("cp.async.wait_group 0;\n" ::: "memory"); }
__device__ __forceinline__ void cp_wait1()  { asm volatile("cp.async.wait_group 1;\n" ::: "memory"); }

// stage one 16x512 fp32 tile (32KB) : 512 threads x 4 float4
__device__ __forceinline__ void stage_tile(float* buf, const float* src, int tid) {
    #pragma unroll
    for (int i = 0; i < 4; ++i)
        cp16(buf + (tid + i * NTHR) * 4, src + (tid + i * NTHR) * 4);
}

// ---------------- activations (saturation-safe fast forms) ----------------
__device__ __forceinline__ float sigf(float x)   { return __fdividef(1.f, 1.f + __expf(-x)); }
__device__ __forceinline__ float tanh_f(float x) { return __fdividef(2.f, 1.f + __expf(-2.f * x)) - 1.f; }

// ---------------- GEMM micro-kernels (packed f32x2) ----------------
// acc[ri][g] holds the packed pair (col j0, col j0+1) of gate g for batch row r0+ri
__device__ __forceinline__ void mm_tile16(u64 (&acc)[8][4], const float* __restrict__ wt,
                                          const float* __restrict__ A_s, int r0, int j0)
{
    #pragma unroll 4
    for (int kk = 0; kk < 16; ++kk) {
        const float* ar = A_s + kk * APAD + r0;
        float4 a0 = *(const float4*)(ar);
        float4 a1 = *(const float4*)(ar + 4);
        float a[8] = {a0.x, a0.y, a0.z, a0.w, a1.x, a1.y, a1.z, a1.w};
        u64 ap[8];
        #pragma unroll
        for (int ri = 0; ri < 8; ++ri) PACK2(ap[ri], a[ri], a[ri]);
        const float* wr = wt + kk * NG + j0;
        u64 w0 = *(const u64*)(wr);
        u64 w1 = *(const u64*)(wr + NH);
        u64 w2 = *(const u64*)(wr + 2*NH);
        u64 w3 = *(const u64*)(wr + 3*NH);
        #pragma unroll
        for (int ri = 0; ri < 8; ++ri) {
            FMA2(acc[ri][0], ap[ri], w0);
            FMA2(acc[ri][1], ap[ri], w1);
            FMA2(acc[ri][2], ap[ri], w2);
            FMA2(acc[ri][3], ap[ri], w3);
        }
    }
}

// K=2 phase for decoder layer0 (weights resident in smem)
__device__ __forceinline__ void mm_k2(u64 (&acc)[8][4], const float* __restrict__ w_s,
                                      const float* __restrict__ in_s, int r0, int j0)
{
    #pragma unroll
    for (int kk = 0; kk < 2; ++kk) {
        const float* ar = in_s + kk * APAD + r0;
        float4 a0 = *(const float4*)(ar);
        float4 a1 = *(const float4*)(ar + 4);
        float a[8] = {a0.x, a0.y, a0.z, a0.w, a1.x, a1.y, a1.z, a1.w};
        u64 ap[8];
        #pragma unroll
        for (int ri = 0; ri < 8; ++ri) PACK2(ap[ri], a[ri], a[ri]);
        const float* wr = w_s + kk * NG + j0;
        u64 w0 = *(const u64*)(wr);
        u64 w1 = *(const u64*)(wr + NH);
        u64 w2 = *(const u64*)(wr + 2*NH);
        u64 w3 = *(const u64*)(wr + 3*NH);
        #pragma unroll
        for (int ri = 0; ri < 8; ++ri) {
            FMA2(acc[ri][0], ap[ri], w0);
            FMA2(acc[ri][1], ap[ri], w1);
            FMA2(acc[ri][2], ap[ri], w2);
            FMA2(acc[ri][3], ap[ri], w3);
        }
    }
}

// One GEMM phase: stream packed W [nk][512] in 16-row tiles, double-buffered cp.async
__device__ __forceinline__ void gemm_phase(u64 (&acc)[8][4], const float* __restrict__ Wg,
                                           int nk, const float* __restrict__ A_s,
                                           float* __restrict__ wb, int tid, int r0, int j0)
{
    const int nt = nk >> 4;
    stage_tile(wb, Wg, tid); cp_commit();
    if (nt > 1) { stage_tile(wb + 16*NG, Wg + 16*NG, tid); cp_commit(); }
    #pragma unroll 1
    for (int it = 0; it < nt; ++it) {
        if (it + 1 < nt) cp_wait1(); else cp_wait0();
        __syncthreads();
        mm_tile16(acc, wb + (it & 1) * 16*NG, A_s + it * 16 * APAD, r0, j0);
        __syncthreads();
        if (it + 2 < nt) { stage_tile(wb + (it & 1) * 16*NG, Wg + (it + 2) * 16*NG, tid); cp_commit(); }
    }
}

__device__ __forceinline__ void init_acc(u64 (&acc)[8][4], const float* __restrict__ bias_s, int j0) {
    #pragma unroll
    for (int g = 0; g < 4; ++g) {
        u64 b = *(const u64*)(bias_s + g * NH + j0);
        #pragma unroll
        for (int ri = 0; ri < 8; ++ri) acc[ri][g] = b;
    }
}

// sigmoid/tanh gating, c update (smem [row][j]), new h -> smem [j][row]
__device__ __forceinline__ void cell_update(u64 (&acc)[8][4], float* __restrict__ c_s,
                                            float* __restrict__ h_s, int r0, int j0)
{
    float hv0[8], hv1[8];
    #pragma unroll
    for (int ri = 0; ri < 8; ++ri) {
        float i0, i1, f0, f1, g0, g1, o0, o1;
        UNPACK2(i0, i1, acc[ri][0]);
        UNPACK2(f0, f1, acc[ri][1]);
        UNPACK2(g0, g1, acc[ri][2]);
        UNPACK2(o0, o1, acc[ri][3]);
        float2* cp = (float2*)(c_s + (r0 + ri) * CSTR + j0);
        float2 c = *cp;
        float c0v = fmaf(sigf(f0), c.x, sigf(i0) * tanh_f(g0));
        float c1v = fmaf(sigf(f1), c.y, sigf(i1) * tanh_f(g1));
        *cp = make_float2(c0v, c1v);
        hv0[ri] = sigf(o0) * tanh_f(c0v);
        hv1[ri] = sigf(o1) * tanh_f(c1v);
    }
    *(float4*)(h_s + j0 * APAD + r0)           = make_float4(hv0[0], hv0[1], hv0[2], hv0[3]);
    *(float4*)(h_s + j0 * APAD + r0 + 4)       = make_float4(hv0[4], hv0[5], hv0[6], hv0[7]);
    *(float4*)(h_s + (j0 + 1) * APAD + r0)     = make_float4(hv1[0], hv1[1], hv1[2], hv1[3]);
    *(float4*)(h_s + (j0 + 1) * APAD + r0 + 4) = make_float4(hv1[4], hv1[5], hv1[6], hv1[7]);
    __syncthreads();
}

// ---------------- weight repack kernel: row-major (512,K) -> k-major [K][512]; bias sums ----------------
__global__ void pack_kernel(const float* eW_ih0, const float* eW_hh0,
                            const float* eb_ih0, const float* eb_hh0,
                            const float* eW_ih1, const float* eW_hh1,
                            const float* eb_ih1, const float* eb_hh1,
                            const float* dW_ih0, const float* dW_hh0,
                            const float* db_ih0, const float* db_hh0,
                            const float* dW_ih1, const float* dW_hh1,
                            const float* db_ih1, const float* db_hh1)
{
    int bid = blockIdx.x, tid = threadIdx.x;
    const float* src = nullptr; float* dst = nullptr; int K = 0;
    switch (bid) {
        case 0:  src = eW_ih0; dst = g_pack + OFS_EWIH0; K = 16;  break;
        case 1:  src = eW_hh0; dst = g_pack + OFS_EWHH0; K = 128; break;
        case 2:  src = eW_ih1; dst = g_pack + OFS_EWIH1; K = 128; break;
        case 3:  src = eW_hh1; dst = g_pack + OFS_EWHH1; K = 128; break;
        case 4:  src = dW_ih0; dst = g_pack + OFS_DWIH0; K = 2;   break;
        case 5:  src = dW_hh0; dst = g_pack + OFS_DWHH0; K = 128; break;
        case 6:  src = dW_ih1; dst = g_pack + OFS_DWIH1; K = 128; break;
        case 7:  src = dW_hh1; dst = g_pack + OFS_DWHH1; K = 128; break;
        case 8:  for (int i = tid; i < NG; i += blockDim.x) g_pack[OFS_BE0 + i] = eb_ih0[i] + eb_hh0[i]; return;
        case 9:  for (int i = tid; i < NG; i += blockDim.x) g_pack[OFS_BE1 + i] = eb_ih1[i] + eb_hh1[i]; return;
        case 10: for (int i = tid; i < NG; i += blockDim.x) g_pack[OFS_BD0 + i] = db_ih0[i] + db_hh0[i]; return;
        case 11: for (int i = tid; i < NG; i += blockDim.x) g_pack[OFS_BD1 + i] = db_ih1[i] + db_hh1[i]; return;
        default: return;
    }
    int n = K * NG;
    for (int i = tid; i < n; i += blockDim.x) {
        int k = i / NG, c = i % NG;
        dst[i] = src[c * K + k];    // transpose to k-major
    }
}

// ---------------- fused encoder+decoder persistent kernel ----------------
__global__ void __launch_bounds__(NTHR, 1)
lstm_kernel(const float* __restrict__ x, const int* __restrict__ tlp,
            const float* __restrict__ fcW, const float* __restrict__ fcb,
            float* __restrict__ out)
{
    extern __shared__ float sm[];
    float* h0_s  = sm + SH_H0;
    float* h1_s  = sm + SH_H1;
    float* c0_s  = sm + SH_C0;
    float* c1_s  = sm + SH_C1;
    float* x_s   = sm + SH_X;
    float* wb    = sm + SH_WB;
    float* be0_s = sm + SH_BE0;
    float* be1_s = sm + SH_BE1;
    float* bd0_s = sm + SH_BD0;
    float* bd1_s = sm + SH_BD1;
    float* dw0_s = sm + SH_DW0;
    float* fcw_s = sm + SH_FCW;
    float* fcb_s = sm + SH_FCB;

    const int tid = threadIdx.x;
    const int b0  = blockIdx.x * MT;
    const int r0  = (tid >> 6) * 8;     // 8 batch rows per thread (warp-uniform)
    const int j0  = (tid & 63) * 2;     // 2 adjacent hidden cols per thread

    // preload constants into smem
    for (int i = tid; i < NG; i += NTHR) {
        be0_s[i] = g_pack[OFS_BE0 + i];
        be1_s[i] = g_pack[OFS_BE1 + i];
        bd0_s[i] = g_pack[OFS_BD0 + i];
        bd1_s[i] = g_pack[OFS_BD1 + i];
    }
    for (int i = tid; i < 2 * NG; i += NTHR) dw0_s[i] = g_pack[OFS_DWIH0 + i];
    for (int i = tid; i < NOUT * NH; i += NTHR) fcw_s[i] = fcW[i];
    if (tid < NOUT) fcb_s[tid] = fcb[tid];
    // zero states
    for (int i = tid; i < NH * APAD; i += NTHR) { h0_s[i] = 0.f; h1_s[i] = 0.f; }
    for (int i = tid; i < MT * CSTR; i += NTHR) { c0_s[i] = 0.f; c1_s[i] = 0.f; }
    __syncthreads();

    const int tl = *tlp;
    u64 acc[8][4];

    // ================= encoder: 100 steps, 2 layers, fused =================
    #pragma unroll 1
    for (int t = 0; t < NTT; ++t) {
        {   // stage x_t transposed into x_s[k][row]
            int r = tid >> 3, i2 = (tid & 7) * 2;
            float2 v = *(const float2*)(x + ((size_t)(b0 + r) * NTT + t) * NIN + i2);
            x_s[i2 * APAD + r]       = v.x;
            x_s[(i2 + 1) * APAD + r] = v.y;
        }
        __syncthreads();
        // layer 0: gates = x @ Wih0^T + h0 @ Whh0^T + b
        init_acc(acc, be0_s, j0);
        gemm_phase(acc, g_pack + OFS_EWIH0, 16,  x_s,  wb, tid, r0, j0);
        gemm_phase(acc, g_pack + OFS_EWHH0, 128, h0_s, wb, tid, r0, j0);
        cell_update(acc, c0_s, h0_s, r0, j0);
        // layer 1: gates = h0_new @ Wih1^T + h1 @ Whh1^T + b
        init_acc(acc, be1_s, j0);
        gemm_phase(acc, g_pack + OFS_EWIH1, 128, h0_s, wb, tid, r0, j0);
        gemm_phase(acc, g_pack + OFS_EWHH1, 128, h1_s, wb, tid, r0, j0);
        cell_update(acc, c1_s, h1_s, r0, j0);
    }

    // decoder initial input: x[:, T-1, 0:2]
    if (tid < 2 * MT) {
        int r = tid >> 1, o = tid & 1;
        x_s[o * APAD + r] = x[((size_t)(b0 + r) * NTT + (NTT - 1)) * NIN + o];
    }
    __syncthreads();

    // ================= decoder: tl steps, 2 layers + fc feedback =================
    #pragma unroll 1
    for (int t = 0; t < tl; ++t) {
        // layer 0: K=2 input phase (smem weights) + recurrent phase
        init_acc(acc, bd0_s, j0);
        mm_k2(acc, dw0_s, x_s, r0, j0);
        gemm_phase(acc, g_pack + OFS_DWHH0, 128, h0_s, wb, tid, r0, j0);
        cell_update(acc, c0_s, h0_s, r0, j0);
        // layer 1
        init_acc(acc, bd1_s, j0);
        gemm_phase(acc, g_pack + OFS_DWIH1, 128, h0_s, wb, tid, r0, j0);
        gemm_phase(acc, g_pack + OFS_DWHH1, 128, h1_s, wb, tid, r0, j0);
        cell_update(acc, c1_s, h1_s, r0, j0);
        // fc: out = h1 @ fcW^T + fcb ; write output + feedback
        if (tid < 2 * MT) {
            int r = tid >> 1, o = tid & 1;
            float s = fcb_s[o];
            #pragma unroll 8
            for (int k = 0; k < NH; ++k)
                s = fmaf(h1_s[k * APAD + r], fcw_s[o * NH + k], s);
            out[((size_t)(b0 + r) * tl + t) * NOUT + o] = s;
            x_s[o * APAD + r] = s;
        }
        __syncthreads();
    }
}

// ---------------- launch ----------------
extern "C" void kernel_launch(void* const* d_in, const int* in_sizes, int n_in,
                              void* d_out, int out_size)
{
    (void)in_sizes; (void)n_in; (void)out_size;
    const float* x      = (const float*)d_in[0];
    const int*   tl     = (const int*)  d_in[1];
    const float* eW_ih0 = (const float*)d_in[2];
    const float* eW_hh0 = (const float*)d_in[3];
    const float* eb_ih0 = (const float*)d_in[4];
    const float* eb_hh0 = (const float*)d_in[5];
    const float* eW_ih1 = (const float*)d_in[6];
    const float* eW_hh1 = (const float*)d_in[7];
    const float* eb_ih1 = (const float*)d_in[8];
    const float* eb_hh1 = (const float*)d_in[9];
    const float* dW_ih0 = (const float*)d_in[10];
    const float* dW_hh0 = (const float*)d_in[11];
    const float* db_ih0 = (const float*)d_in[12];
    const float* db_hh0 = (const float*)d_in[13];
    const float* dW_ih1 = (const float*)d_in[14];
    const float* dW_hh1 = (const float*)d_in[15];
    const float* db_ih1 = (const float*)d_in[16];
    const float* db_hh1 = (const float*)d_in[17];
    const float* fcW    = (const float*)d_in[18];
    const float* fcb    = (const float*)d_in[19];

    cudaFuncSetAttribute(lstm_kernel, cudaFuncAttributeMaxDynamicSharedMemorySize, SH_BYTES);

    pack_kernel<<<12, 256>>>(eW_ih0, eW_hh0, eb_ih0, eb_hh0,
                             eW_ih1, eW_hh1, eb_ih1, eb_hh1,
                             dW_ih0, dW_hh0, db_ih0, db_hh0,
                             dW_ih1, dW_hh1, db_ih1, db_hh1);

    lstm_kernel<<<NB / MT, NTHR, SH_BYTES>>>(x, tl, fcW, fcb, (float*)d_out);
}

// round 4
// speedup vs baseline: 1.0405x; 1.0041x over previous
#include <cuda_runtime.h>
#include <cstdint>
#include <cstddef>

typedef unsigned long long u64;

// ---------------- problem constants ----------------
#define NB   8192   // batch
#define NTT  100    // encoder time steps
#define NIN  16     // encoder input dim
#define NH   128    // hidden
#define NG   512    // 4*H gate rows
#define NOUT 2      // fc output dim

#define MT   32     // batch rows per CTA
#define NTHR 256    // threads per CTA
#define APAD 36     // padded row stride for [k][row] activation buffers (mult of 4)
#define KT   8      // k-rows per weight tile

// ---------------- packed f32x2 helpers (Blackwell) ----------------
#define FMA2(d, a, b) asm("fma.rn.f32x2 %0, %1, %2, %0;" : "+l"(d) : "l"(a), "l"(b))
#define PACK2(d, lo, hi) asm("mov.b64 %0, {%1, %2};" : "=l"(d) : "f"(lo), "f"(hi))
#define UNPACK2(lo, hi, v) asm("mov.b64 {%0, %1}, %2;" : "=f"(lo), "=f"(hi) : "l"(v))

// ---------------- packed weight scratch (k-major [K][512]) ----------------
#define OFS_EWIH0 0
#define OFS_EWHH0 (OFS_EWIH0 + 16*NG)
#define OFS_EWIH1 (OFS_EWHH0 + NH*NG)
#define OFS_EWHH1 (OFS_EWIH1 + NH*NG)
#define OFS_DWIH0 (OFS_EWHH1 + NH*NG)
#define OFS_DWHH0 (OFS_DWIH0 + 2*NG)
#define OFS_DWIH1 (OFS_DWHH0 + NH*NG)
#define OFS_DWHH1 (OFS_DWIH1 + NH*NG)
#define OFS_BE0   (OFS_DWHH1 + NH*NG)
#define OFS_BE1   (OFS_BE0 + NG)
#define OFS_BD0   (OFS_BE1 + NG)
#define OFS_BD1   (OFS_BD0 + NG)
#define PACK_TOTAL (OFS_BD1 + NG)

__device__ float g_pack[PACK_TOTAL];

// ---------------- shared memory layout (floats) ----------------
#define SH_H0  0
#define SH_H1  (SH_H0 + NH*APAD)          // 4608
#define SH_X   (SH_H1 + NH*APAD)          // [16][APAD], also decoder input [2][APAD]
#define SH_WB  (SH_X + NIN*APAD)          // 2 x (8x512) weight tile double buffer
#define SH_C   (SH_WB + 2*KT*NG)          // 2 states x 256 thr x 16, warp-interleaved
#define SH_FCW (SH_C + 2*NTHR*16)         // [2][128]
#define SH_FCB (SH_FCW + NOUT*NH)
#define SH_TOTAL (SH_FCB + 8)
#define SH_BYTES (SH_TOTAL * 4)           // ~105.8 KB -> 2 CTAs/SM

// ---------------- cp.async helpers ----------------
__device__ __forceinline__ void cp16(void* dst, const void* src) {
    unsigned d = (unsigned)__cvta_generic_to_shared(dst);
    asm volatile("cp.async.cg.shared.global [%0], [%1], 16;\n" :: "r"(d), "l"(src) : "memory");
}
__device__ __forceinline__ void cp_commit() { asm volatile("cp.async.commit_group;\n" ::: "memory"); }
__device__ __forceinline__ void cp_wait0()  { asm volatile("cp.async.wait_group 0;\n" ::: "memory"); }

// stage one 8x512 fp32 tile (16KB): 256 threads x 4 float4
__device__ __forceinline__ void stage_tile(float* buf, const float* src, int tid) {
    #pragma unroll
    for (int i = 0; i < 4; ++i)
        cp16(buf + (tid + i * NTHR) * 4, src + (tid + i * NTHR) * 4);
}

// ---------------- activations: MUFU tanh ----------------
__device__ __forceinline__ float tanhap(float x) {
    float y; asm("tanh.approx.f32 %0, %1;" : "=f"(y) : "f"(x)); return y;
}
__device__ __forceinline__ float sigap(float x) { return fmaf(tanhap(0.5f * x), 0.5f, 0.5f); }

// ---------------- GEMM micro-kernels (packed f32x2) ----------------
// acc[ri][g] = packed pair (col j0, j0+1) of gate g, batch row r0+ri
__device__ __forceinline__ void mm_tile8(u64 (&acc)[8][4], const float* __restrict__ wt,
                                         const float* __restrict__ A_s, int r0, int j0)
{
    #pragma unroll 4
    for (int kk = 0; kk < KT; ++kk) {
        const float* ar = A_s + kk * APAD + r0;
        float4 a0 = *(const float4*)(ar);
        float4 a1 = *(const float4*)(ar + 4);
        float a[8] = {a0.x, a0.y, a0.z, a0.w, a1.x, a1.y, a1.z, a1.w};
        u64 ap[8];
        #pragma unroll
        for (int ri = 0; ri < 8; ++ri) PACK2(ap[ri], a[ri], a[ri]);
        const float* wr = wt + kk * NG + j0;
        u64 w0 = *(const u64*)(wr);
        u64 w1 = *(const u64*)(wr + NH);
        u64 w2 = *(const u64*)(wr + 2*NH);
        u64 w3 = *(const u64*)(wr + 3*NH);
        #pragma unroll
        for (int ri = 0; ri < 8; ++ri) {
            FMA2(acc[ri][0], ap[ri], w0);
            FMA2(acc[ri][1], ap[ri], w1);
            FMA2(acc[ri][2], ap[ri], w2);
            FMA2(acc[ri][3], ap[ri], w3);
        }
    }
}

// K=2 phase for decoder layer0, weights read from global (L1-resident)
__device__ __forceinline__ void mm_k2(u64 (&acc)[8][4], const float* __restrict__ wg,
                                      const float* __restrict__ in_s, int r0, int j0)
{
    #pragma unroll
    for (int kk = 0; kk < 2; ++kk) {
        const float* ar = in_s + kk * APAD + r0;
        float4 a0 = *(const float4*)(ar);
        float4 a1 = *(const float4*)(ar + 4);
        float a[8] = {a0.x, a0.y, a0.z, a0.w, a1.x, a1.y, a1.z, a1.w};
        u64 ap[8];
        #pragma unroll
        for (int ri = 0; ri < 8; ++ri) PACK2(ap[ri], a[ri], a[ri]);
        const float* wr = wg + kk * NG + j0;
        u64 w0 = *(const u64*)(wr);
        u64 w1 = *(const u64*)(wr + NH);
        u64 w2 = *(const u64*)(wr + 2*NH);
        u64 w3 = *(const u64*)(wr + 3*NH);
        #pragma unroll
        for (int ri = 0; ri < 8; ++ri) {
            FMA2(acc[ri][0], ap[ri], w0);
            FMA2(acc[ri][1], ap[ri], w1);
            FMA2(acc[ri][2], ap[ri], w2);
            FMA2(acc[ri][3], ap[ri], w3);
        }
    }
}

// One GEMM phase over packed W [nk][512], 8-row tiles, double buffer,
// SINGLE __syncthreads per tile: stage tile i+1 AFTER barrier B_i into the
// buffer consumed at iter i-1 (all threads passed B_i only after finishing
// consumption of tile i-1, so the overwrite is race-free).
// NOTE: requires nt even so the next phase's prologue (buf0) never collides
// with this phase's last tile (buf1). nk ∈ {16,128} -> nt ∈ {2,16}. OK.
// The LAST tile's compute is left un-barriered; callers that subsequently
// write buffers read here (h/x) must sync first (cell_update does).
__device__ __forceinline__ void gemm_phase(u64 (&acc)[8][4], const float* __restrict__ Wg,
                                           int nk, const float* __restrict__ A_s,
                                           float* __restrict__ wb, int tid, int r0, int j0)
{
    const int nt = nk >> 3;
    stage_tile(wb, Wg, tid); cp_commit();
    #pragma unroll 1
    for (int it = 0; it < nt; ++it) {
        cp_wait0();
        __syncthreads();
        if (it + 1 < nt) { stage_tile(wb + ((it + 1) & 1) * KT * NG, Wg + (it + 1) * KT * NG, tid); cp_commit(); }
        mm_tile8(acc, wb + (it & 1) * KT * NG, A_s + it * KT * APAD, r0, j0);
    }
}

__device__ __forceinline__ void init_acc(u64 (&acc)[8][4], const float* __restrict__ bias_g, int j0) {
    #pragma unroll
    for (int g = 0; g < 4; ++g) {
        u64 b = *(const u64*)(bias_g + g * NH + j0);
        #pragma unroll
        for (int ri = 0; ri < 8; ++ri) acc[ri][g] = b;
    }
}

// gating + c update (warp-interleaved private smem) + h -> smem [j][row]
// Leading sync: all threads must finish READING old h (last gemm tile) before
// anyone overwrites h_s with the new value.
__device__ __forceinline__ void cell_update(u64 (&acc)[8][4], float* __restrict__ cpriv,
                                            float* __restrict__ h_s, int r0, int j0)
{
    float hv0[8], hv1[8];
    #pragma unroll
    for (int ri = 0; ri < 8; ++ri) {
        float i0, i1, f0, f1, g0, g1, o0, o1;
        UNPACK2(i0, i1, acc[ri][0]);
        UNPACK2(f0, f1, acc[ri][1]);
        UNPACK2(g0, g1, acc[ri][2]);
        UNPACK2(o0, o1, acc[ri][3]);
        float c0o = cpriv[(2*ri+0) * 32];
        float c1o = cpriv[(2*ri+1) * 32];
        float c0v = fmaf(sigap(f0), c0o, sigap(i0) * tanhap(g0));
        float c1v = fmaf(sigap(f1), c1o, sigap(i1) * tanhap(g1));
        cpriv[(2*ri+0) * 32] = c0v;
        cpriv[(2*ri+1) * 32] = c1v;
        hv0[ri] = sigap(o0) * tanhap(c0v);
        hv1[ri] = sigap(o1) * tanhap(c1v);
    }
    __syncthreads();   // drain readers of old h before overwrite
    *(float4*)(h_s + j0 * APAD + r0)           = make_float4(hv0[0], hv0[1], hv0[2], hv0[3]);
    *(float4*)(h_s + j0 * APAD + r0 + 4)       = make_float4(hv0[4], hv0[5], hv0[6], hv0[7]);
    *(float4*)(h_s + (j0 + 1) * APAD + r0)     = make_float4(hv1[0], hv1[1], hv1[2], hv1[3]);
    *(float4*)(h_s + (j0 + 1) * APAD + r0 + 4) = make_float4(hv1[4], hv1[5], hv1[6], hv1[7]);
    __syncthreads();   // publish new h
}

// ---------------- weight repack kernel: row-major (512,K) -> k-major [K][512]; bias sums ----------------
__global__ void pack_kernel(const float* eW_ih0, const float* eW_hh0,
                            const float* eb_ih0, const float* eb_hh0,
                            const float* eW_ih1, const float* eW_hh1,
                            const float* eb_ih1, const float* eb_hh1,
                            const float* dW_ih0, const float* dW_hh0,
                            const float* db_ih0, const float* db_hh0,
                            const float* dW_ih1, const float* dW_hh1,
                            const float* db_ih1, const float* db_hh1)
{
    int bid = blockIdx.x, tid = threadIdx.x;
    const float* src = nullptr; float* dst = nullptr; int K = 0;
    switch (bid) {
        case 0:  src = eW_ih0; dst = g_pack + OFS_EWIH0; K = 16;  break;
        case 1:  src = eW_hh0; dst = g_pack + OFS_EWHH0; K = 128; break;
        case 2:  src = eW_ih1; dst = g_pack + OFS_EWIH1; K = 128; break;
        case 3:  src = eW_hh1; dst = g_pack + OFS_EWHH1; K = 128; break;
        case 4:  src = dW_ih0; dst = g_pack + OFS_DWIH0; K = 2;   break;
        case 5:  src = dW_hh0; dst = g_pack + OFS_DWHH0; K = 128; break;
        case 6:  src = dW_ih1; dst = g_pack + OFS_DWIH1; K = 128; break;
        case 7:  src = dW_hh1; dst = g_pack + OFS_DWHH1; K = 128; break;
        case 8:  for (int i = tid; i < NG; i += blockDim.x) g_pack[OFS_BE0 + i] = eb_ih0[i] + eb_hh0[i]; return;
        case 9:  for (int i = tid; i < NG; i += blockDim.x) g_pack[OFS_BE1 + i] = eb_ih1[i] + eb_hh1[i]; return;
        case 10: for (int i = tid; i < NG; i += blockDim.x) g_pack[OFS_BD0 + i] = db_ih0[i] + db_hh0[i]; return;
        case 11: for (int i = tid; i < NG; i += blockDim.x) g_pack[OFS_BD1 + i] = db_ih1[i] + db_hh1[i]; return;
        default: return;
    }
    int n = K * NG;
    for (int i = tid; i < n; i += blockDim.x) {
        int k = i / NG, c = i % NG;
        dst[i] = src[c * K + k];    // transpose to k-major
    }
}

// ---------------- fused encoder+decoder persistent kernel ----------------
__global__ void __launch_bounds__(NTHR, 2)
lstm_kernel(const float* __restrict__ x, const int* __restrict__ tlp,
            const float* __restrict__ fcW, const float* __restrict__ fcb,
            float* __restrict__ out)
{
    extern __shared__ float sm[];
    float* h0_s  = sm + SH_H0;
    float* h1_s  = sm + SH_H1;
    float* x_s   = sm + SH_X;
    float* wb    = sm + SH_WB;
    float* fcw_s = sm + SH_FCW;
    float* fcb_s = sm + SH_FCB;

    const int tid = threadIdx.x;
    const int b0  = blockIdx.x * MT;
    const int r0  = (tid >> 6) * 8;     // 8 batch rows per thread (warp-uniform)
    const int j0  = (tid & 63) * 2;     // 2 adjacent hidden cols per thread

    // private c state: warp-interleaved, conflict-free (lane stride 1, elem stride 32)
    float* c0p = sm + SH_C + (tid >> 5) * 512 + (tid & 31);
    float* c1p = c0p + NTHR * 16;

    for (int i = tid; i < NOUT * NH; i += NTHR) fcw_s[i] = fcW[i];
    if (tid < NOUT) fcb_s[tid] = fcb[tid];
    for (int i = tid; i < NH * APAD; i += NTHR) { h0_s[i] = 0.f; h1_s[i] = 0.f; }
    for (int i = tid; i < 2 * NTHR * 16; i += NTHR) sm[SH_C + i] = 0.f;
    __syncthreads();

    const int tl = *tlp;
    u64 acc[8][4];

    // ================= encoder: 100 steps, 2 layers, fused =================
    #pragma unroll 1
    for (int t = 0; t < NTT; ++t) {
        {   // stage x_t transposed into x_s[k][row]
            int r = tid >> 3, i2 = (tid & 7) * 2;
            float2 v = *(const float2*)(x + ((size_t)(b0 + r) * NTT + t) * NIN + i2);
            x_s[i2 * APAD + r]       = v.x;
            x_s[(i2 + 1) * APAD + r] = v.y;
        }
        __syncthreads();
        // layer 0
        init_acc(acc, g_pack + OFS_BE0, j0);
        gemm_phase(acc, g_pack + OFS_EWIH0, 16,  x_s,  wb, tid, r0, j0);
        gemm_phase(acc, g_pack + OFS_EWHH0, 128, h0_s, wb, tid, r0, j0);
        cell_update(acc, c0p, h0_s, r0, j0);
        // layer 1
        init_acc(acc, g_pack + OFS_BE1, j0);
        gemm_phase(acc, g_pack + OFS_EWIH1, 128, h0_s, wb, tid, r0, j0);
        gemm_phase(acc, g_pack + OFS_EWHH1, 128, h1_s, wb, tid, r0, j0);
        cell_update(acc, c1p, h1_s, r0, j0);
    }

    // decoder initial input: x[:, T-1, 0:2]
    if (tid < 2 * MT) {
        int r = tid >> 1, o = tid & 1;
        x_s[o * APAD + r] = x[((size_t)(b0 + r) * NTT + (NTT - 1)) * NIN + o];
    }
    __syncthreads();

    // ================= decoder: tl steps, 2 layers + fc feedback =================
    #pragma unroll 1
    for (int t = 0; t < tl; ++t) {
        // layer 0
        init_acc(acc, g_pack + OFS_BD0, j0);
        mm_k2(acc, g_pack + OFS_DWIH0, x_s, r0, j0);
        gemm_phase(acc, g_pack + OFS_DWHH0, 128, h0_s, wb, tid, r0, j0);
        cell_update(acc, c0p, h0_s, r0, j0);
        // layer 1
        init_acc(acc, g_pack + OFS_BD1, j0);
        gemm_phase(acc, g_pack + OFS_DWIH1, 128, h0_s, wb, tid, r0, j0);
        gemm_phase(acc, g_pack + OFS_DWHH1, 128, h1_s, wb, tid, r0, j0);
        cell_update(acc, c1p, h1_s, r0, j0);
        // fc: out = h1 @ fcW^T + fcb ; write output + feedback
        if (tid < 2 * MT) {
            int r = tid >> 1, o = tid & 1;
            float s = fcb_s[o];
            #pragma unroll 8
            for (int k = 0; k < NH; ++k)
                s = fmaf(h1_s[k * APAD + r], fcw_s[o * NH + k], s);
            out[((size_t)(b0 + r) * tl + t) * NOUT + o] = s;
            x_s[o * APAD + r] = s;
        }
        __syncthreads();
    }
}

// ---------------- launch ----------------
extern "C" void kernel_launch(void* const* d_in, const int* in_sizes, int n_in,
                              void* d_out, int out_size)
{
    (void)in_sizes; (void)n_in; (void)out_size;
    const float* x      = (const float*)d_in[0];
    const int*   tl     = (const int*)  d_in[1];
    const float* eW_ih0 = (const float*)d_in[2];
    const float* eW_hh0 = (const float*)d_in[3];
    const float* eb_ih0 = (const float*)d_in[4];
    const float* eb_hh0 = (const float*)d_in[5];
    const float* eW_ih1 = (const float*)d_in[6];
    const float* eW_hh1 = (const float*)d_in[7];
    const float* eb_ih1 = (const float*)d_in[8];
    const float* eb_hh1 = (const float*)d_in[9];
    const float* dW_ih0 = (const float*)d_in[10];
    const float* dW_hh0 = (const float*)d_in[11];
    const float* db_ih0 = (const float*)d_in[12];
    const float* db_hh0 = (const float*)d_in[13];
    const float* dW_ih1 = (const float*)d_in[14];
    const float* dW_hh1 = (const float*)d_in[15];
    const float* db_ih1 = (const float*)d_in[16];
    const float* db_hh1 = (const float*)d_in[17];
    const float* fcW    = (const float*)d_in[18];
    const float* fcb    = (const float*)d_in[19];

    cudaFuncSetAttribute(lstm_kernel, cudaFuncAttributeMaxDynamicSharedMemorySize, SH_BYTES);

    pack_kernel<<<12, 256>>>(eW_ih0, eW_hh0, eb_ih0, eb_hh0,
                             eW_ih1, eW_hh1, eb_ih1, eb_hh1,
                             dW_ih0, dW_hh0, db_ih0, db_hh0,
                             dW_ih1, dW_hh1, db_ih1, db_hh1);

    lstm_kernel<<<NB / MT, NTHR, SH_BYTES>>>(x, tl, fcW, fcb, (float*)d_out);
}

// round 6
// speedup vs baseline: 1.0411x; 1.0005x over previous
#include <cuda_runtime.h>
#include <cstdint>
#include <cstddef>

typedef unsigned long long u64;

// ---------------- problem constants ----------------
#define NB   8192   // batch
#define NTT  100    // encoder time steps
#define NIN  16     // encoder input dim
#define NH   128    // hidden
#define NG   512    // 4*H gate rows
#define NOUT 2      // fc output dim

#define MT   32     // batch rows per CTA
#define NTHR 256    // threads per CTA
#define APAD 36     // padded row stride for [k][row] activation buffers (mult of 4)
#define KT   8      // k-rows per weight tile

// ---------------- packed f32x2 helpers (Blackwell) ----------------
#define FMA2(d, a, b) asm("fma.rn.f32x2 %0, %1, %2, %0;" : "+l"(d) : "l"(a), "l"(b))
#define PACK2(d, lo, hi) asm("mov.b64 %0, {%1, %2};" : "=l"(d) : "f"(lo), "f"(hi))
#define UNPACK2(lo, hi, v) asm("mov.b64 {%0, %1}, %2;" : "=f"(lo), "=f"(hi) : "l"(v))

// ---------------- packed weight scratch (k-major [K][512]) ----------------
#define OFS_EWIH0 0
#define OFS_EWHH0 (OFS_EWIH0 + 16*NG)
#define OFS_EWIH1 (OFS_EWHH0 + NH*NG)
#define OFS_EWHH1 (OFS_EWIH1 + NH*NG)
#define OFS_DWIH0 (OFS_EWHH1 + NH*NG)
#define OFS_DWHH0 (OFS_DWIH0 + 2*NG)
#define OFS_DWIH1 (OFS_DWHH0 + NH*NG)
#define OFS_DWHH1 (OFS_DWIH1 + NH*NG)
#define OFS_BE0   (OFS_DWHH1 + NH*NG)
#define OFS_BE1   (OFS_BE0 + NG)
#define OFS_BD0   (OFS_BE1 + NG)
#define OFS_BD1   (OFS_BD0 + NG)
#define PACK_TOTAL (OFS_BD1 + NG)

__device__ float g_pack[PACK_TOTAL];

// ---------------- shared memory layout (floats) ----------------
#define SH_H0  0
#define SH_H1  (SH_H0 + NH*APAD)          // 4608
#define SH_X   (SH_H1 + NH*APAD)          // [16][APAD], also decoder input [2][APAD]
#define SH_WB  (SH_X + NIN*APAD)          // 2 x (8x512) weight tile double buffer
#define SH_C   (SH_WB + 2*KT*NG)          // 2 states x 256 thr x 16, warp-interleaved
#define SH_FCW (SH_C + 2*NTHR*16)         // [2][128]
#define SH_FCB (SH_FCW + NOUT*NH)
#define SH_TOTAL (SH_FCB + 8)
#define SH_BYTES (SH_TOTAL * 4)           // ~105.8 KB -> 2 CTAs/SM

// ---------------- cp.async helpers ----------------
__device__ __forceinline__ void cp16(void* dst, const void* src) {
    unsigned d = (unsigned)__cvta_generic_to_shared(dst);
    asm volatile("cp.async.cg.shared.global [%0], [%1], 16;\n" :: "r"(d), "l"(src) : "memory");
}
__device__ __forceinline__ void cp_commit() { asm volatile("cp.async.commit_group;\n" ::: "memory"); }
__device__ __forceinline__ void cp_wait0()  { asm volatile("cp.async.wait_group 0;\n" ::: "memory"); }

// stage one 8x512 fp32 tile (16KB): 256 threads x 4 float4
__device__ __forceinline__ void stage_tile(float* buf, const float* src, int tid) {
    #pragma unroll
    for (int i = 0; i < 4; ++i)
        cp16(buf + (tid + i * NTHR) * 4, src + (tid + i * NTHR) * 4);
}

// ---------------- activations: MUFU tanh ----------------
__device__ __forceinline__ float tanhap(float x) {
    float y; asm("tanh.approx.f32 %0, %1;" : "=f"(y) : "f"(x)); return y;
}
__device__ __forceinline__ float sigap(float x) { return fmaf(tanhap(0.5f * x), 0.5f, 0.5f); }

// ---------------- GEMM micro-kernels (packed f32x2) ----------------
// acc[ri][g] = packed pair (col j0, j0+1) of gate g, batch row r0+ri
__device__ __forceinline__ void mm_tile8(u64 (&acc)[8][4], const float* __restrict__ wt,
                                         const float* __restrict__ A_s, int r0, int j0)
{
    #pragma unroll 4
    for (int kk = 0; kk < KT; ++kk) {
        const float* ar = A_s + kk * APAD + r0;
        float4 a0 = *(const float4*)(ar);
        float4 a1 = *(const float4*)(ar + 4);
        float a[8] = {a0.x, a0.y, a0.z, a0.w, a1.x, a1.y, a1.z, a1.w};
        u64 ap[8];
        #pragma unroll
        for (int ri = 0; ri < 8; ++ri) PACK2(ap[ri], a[ri], a[ri]);
        const float* wr = wt + kk * NG + j0;
        u64 w0 = *(const u64*)(wr);
        u64 w1 = *(const u64*)(wr + NH);
        u64 w2 = *(const u64*)(wr + 2*NH);
        u64 w3 = *(const u64*)(wr + 3*NH);
        #pragma unroll
        for (int ri = 0; ri < 8; ++ri) {
            FMA2(acc[ri][0], ap[ri], w0);
            FMA2(acc[ri][1], ap[ri], w1);
            FMA2(acc[ri][2], ap[ri], w2);
            FMA2(acc[ri][3], ap[ri], w3);
        }
    }
}

// K=2 phase for decoder layer0, weights read from global (L1-resident)
__device__ __forceinline__ void mm_k2(u64 (&acc)[8][4], const float* __restrict__ wg,
                                      const float* __restrict__ in_s, int r0, int j0)
{
    #pragma unroll
    for (int kk = 0; kk < 2; ++kk) {
        const float* ar = in_s + kk * APAD + r0;
        float4 a0 = *(const float4*)(ar);
        float4 a1 = *(const float4*)(ar + 4);
        float a[8] = {a0.x, a0.y, a0.z, a0.w, a1.x, a1.y, a1.z, a1.w};
        u64 ap[8];
        #pragma unroll
        for (int ri = 0; ri < 8; ++ri) PACK2(ap[ri], a[ri], a[ri]);
        const float* wr = wg + kk * NG + j0;
        u64 w0 = *(const u64*)(wr);
        u64 w1 = *(const u64*)(wr + NH);
        u64 w2 = *(const u64*)(wr + 2*NH);
        u64 w3 = *(const u64*)(wr + 3*NH);
        #pragma unroll
        for (int ri = 0; ri < 8; ++ri) {
            FMA2(acc[ri][0], ap[ri], w0);
            FMA2(acc[ri][1], ap[ri], w1);
            FMA2(acc[ri][2], ap[ri], w2);
            FMA2(acc[ri][3], ap[ri], w3);
        }
    }
}

// One GEMM phase over packed W [nk][512], 8-row tiles, double buffer,
// SINGLE __syncthreads per tile: stage tile i+1 AFTER barrier B_i into the
// buffer consumed at iter i-1 (all threads passed B_i only after finishing
// consumption of tile i-1, so the overwrite is race-free).
// NOTE: requires nt even so the next phase's prologue (buf0) never collides
// with this phase's last tile (buf1). nk ∈ {16,128} -> nt ∈ {2,16}. OK.
// The LAST tile's compute is left un-barriered; callers that subsequently
// write buffers read here (h/x) must sync first (cell_update does).
__device__ __forceinline__ void gemm_phase(u64 (&acc)[8][4], const float* __restrict__ Wg,
                                           int nk, const float* __restrict__ A_s,
                                           float* __restrict__ wb, int tid, int r0, int j0)
{
    const int nt = nk >> 3;
    stage_tile(wb, Wg, tid); cp_commit();
    #pragma unroll 1
    for (int it = 0; it < nt; ++it) {
        cp_wait0();
        __syncthreads();
        if (it + 1 < nt) { stage_tile(wb + ((it + 1) & 1) * KT * NG, Wg + (it + 1) * KT * NG, tid); cp_commit(); }
        mm_tile8(acc, wb + (it & 1) * KT * NG, A_s + it * KT * APAD, r0, j0);
    }
}

__device__ __forceinline__ void init_acc(u64 (&acc)[8][4], const float* __restrict__ bias_g, int j0) {
    #pragma unroll
    for (int g = 0; g < 4; ++g) {
        u64 b = *(const u64*)(bias_g + g * NH + j0);
        #pragma unroll
        for (int ri = 0; ri < 8; ++ri) acc[ri][g] = b;
    }
}

// gating + c update (warp-interleaved private smem) + h -> smem [j][row]
// Leading sync: all threads must finish READING old h (last gemm tile) before
// anyone overwrites h_s with the new value.
__device__ __forceinline__ void cell_update(u64 (&acc)[8][4], float* __restrict__ cpriv,
                                            float* __restrict__ h_s, int r0, int j0)
{
    float hv0[8], hv1[8];
    #pragma unroll
    for (int ri = 0; ri < 8; ++ri) {
        float i0, i1, f0, f1, g0, g1, o0, o1;
        UNPACK2(i0, i1, acc[ri][0]);
        UNPACK2(f0, f1, acc[ri][1]);
        UNPACK2(g0, g1, acc[ri][2]);
        UNPACK2(o0, o1, acc[ri][3]);
        float c0o = cpriv[(2*ri+0) * 32];
        float c1o = cpriv[(2*ri+1) * 32];
        float c0v = fmaf(sigap(f0), c0o, sigap(i0) * tanhap(g0));
        float c1v = fmaf(sigap(f1), c1o, sigap(i1) * tanhap(g1));
        cpriv[(2*ri+0) * 32] = c0v;
        cpriv[(2*ri+1) * 32] = c1v;
        hv0[ri] = sigap(o0) * tanhap(c0v);
        hv1[ri] = sigap(o1) * tanhap(c1v);
    }
    __syncthreads();   // drain readers of old h before overwrite
    *(float4*)(h_s + j0 * APAD + r0)           = make_float4(hv0[0], hv0[1], hv0[2], hv0[3]);
    *(float4*)(h_s + j0 * APAD + r0 + 4)       = make_float4(hv0[4], hv0[5], hv0[6], hv0[7]);
    *(float4*)(h_s + (j0 + 1) * APAD + r0)     = make_float4(hv1[0], hv1[1], hv1[2], hv1[3]);
    *(float4*)(h_s + (j0 + 1) * APAD + r0 + 4) = make_float4(hv1[4], hv1[5], hv1[6], hv1[7]);
    __syncthreads();   // publish new h
}

// ---------------- weight repack kernel: row-major (512,K) -> k-major [K][512]; bias sums ----------------
__global__ void pack_kernel(const float* eW_ih0, const float* eW_hh0,
                            const float* eb_ih0, const float* eb_hh0,
                            const float* eW_ih1, const float* eW_hh1,
                            const float* eb_ih1, const float* eb_hh1,
                            const float* dW_ih0, const float* dW_hh0,
                            const float* db_ih0, const float* db_hh0,
                            const float* dW_ih1, const float* dW_hh1,
                            const float* db_ih1, const float* db_hh1)
{
    int bid = blockIdx.x, tid = threadIdx.x;
    const float* src = nullptr; float* dst = nullptr; int K = 0;
    switch (bid) {
        case 0:  src = eW_ih0; dst = g_pack + OFS_EWIH0; K = 16;  break;
        case 1:  src = eW_hh0; dst = g_pack + OFS_EWHH0; K = 128; break;
        case 2:  src = eW_ih1; dst = g_pack + OFS_EWIH1; K = 128; break;
        case 3:  src = eW_hh1; dst = g_pack + OFS_EWHH1; K = 128; break;
        case 4:  src = dW_ih0; dst = g_pack + OFS_DWIH0; K = 2;   break;
        case 5:  src = dW_hh0; dst = g_pack + OFS_DWHH0; K = 128; break;
        case 6:  src = dW_ih1; dst = g_pack + OFS_DWIH1; K = 128; break;
        case 7:  src = dW_hh1; dst = g_pack + OFS_DWHH1; K = 128; break;
        case 8:  for (int i = tid; i < NG; i += blockDim.x) g_pack[OFS_BE0 + i] = eb_ih0[i] + eb_hh0[i]; return;
        case 9:  for (int i = tid; i < NG; i += blockDim.x) g_pack[OFS_BE1 + i] = eb_ih1[i] + eb_hh1[i]; return;
        case 10: for (int i = tid; i < NG; i += blockDim.x) g_pack[OFS_BD0 + i] = db_ih0[i] + db_hh0[i]; return;
        case 11: for (int i = tid; i < NG; i += blockDim.x) g_pack[OFS_BD1 + i] = db_ih1[i] + db_hh1[i]; return;
        default: return;
    }
    int n = K * NG;
    for (int i = tid; i < n; i += blockDim.x) {
        int k = i / NG, c = i % NG;
        dst[i] = src[c * K + k];    // transpose to k-major
    }
}

// ---------------- fused encoder+decoder persistent kernel ----------------
__global__ void __launch_bounds__(NTHR, 2)
lstm_kernel(const float* __restrict__ x, const int* __restrict__ tlp,
            const float* __restrict__ fcW, const float* __restrict__ fcb,
            float* __restrict__ out)
{
    extern __shared__ float sm[];
    float* h0_s  = sm + SH_H0;
    float* h1_s  = sm + SH_H1;
    float* x_s   = sm + SH_X;
    float* wb    = sm + SH_WB;
    float* fcw_s = sm + SH_FCW;
    float* fcb_s = sm + SH_FCB;

    const int tid = threadIdx.x;
    const int b0  = blockIdx.x * MT;
    const int r0  = (tid >> 6) * 8;     // 8 batch rows per thread (warp-uniform)
    const int j0  = (tid & 63) * 2;     // 2 adjacent hidden cols per thread

    // private c state: warp-interleaved, conflict-free (lane stride 1, elem stride 32)
    float* c0p = sm + SH_C + (tid >> 5) * 512 + (tid & 31);
    float* c1p = c0p + NTHR * 16;

    for (int i = tid; i < NOUT * NH; i += NTHR) fcw_s[i] = fcW[i];
    if (tid < NOUT) fcb_s[tid] = fcb[tid];
    for (int i = tid; i < NH * APAD; i += NTHR) { h0_s[i] = 0.f; h1_s[i] = 0.f; }
    for (int i = tid; i < 2 * NTHR * 16; i += NTHR) sm[SH_C + i] = 0.f;
    __syncthreads();

    const int tl = *tlp;
    u64 acc[8][4];

    // ================= encoder: 100 steps, 2 layers, fused =================
    #pragma unroll 1
    for (int t = 0; t < NTT; ++t) {
        {   // stage x_t transposed into x_s[k][row]
            int r = tid >> 3, i2 = (tid & 7) * 2;
            float2 v = *(const float2*)(x + ((size_t)(b0 + r) * NTT + t) * NIN + i2);
            x_s[i2 * APAD + r]       = v.x;
            x_s[(i2 + 1) * APAD + r] = v.y;
        }
        __syncthreads();
        // layer 0
        init_acc(acc, g_pack + OFS_BE0, j0);
        gemm_phase(acc, g_pack + OFS_EWIH0, 16,  x_s,  wb, tid, r0, j0);
        gemm_phase(acc, g_pack + OFS_EWHH0, 128, h0_s, wb, tid, r0, j0);
        cell_update(acc, c0p, h0_s, r0, j0);
        // layer 1
        init_acc(acc, g_pack + OFS_BE1, j0);
        gemm_phase(acc, g_pack + OFS_EWIH1, 128, h0_s, wb, tid, r0, j0);
        gemm_phase(acc, g_pack + OFS_EWHH1, 128, h1_s, wb, tid, r0, j0);
        cell_update(acc, c1p, h1_s, r0, j0);
    }

    // decoder initial input: x[:, T-1, 0:2]
    if (tid < 2 * MT) {
        int r = tid >> 1, o = tid & 1;
        x_s[o * APAD + r] = x[((size_t)(b0 + r) * NTT + (NTT - 1)) * NIN + o];
    }
    __syncthreads();

    // ================= decoder: tl steps, 2 layers + fc feedback =================
    #pragma unroll 1
    for (int t = 0; t < tl; ++t) {
        // layer 0
        init_acc(acc, g_pack + OFS_BD0, j0);
        mm_k2(acc, g_pack + OFS_DWIH0, x_s, r0, j0);
        gemm_phase(acc, g_pack + OFS_DWHH0, 128, h0_s, wb, tid, r0, j0);
        cell_update(acc, c0p, h0_s, r0, j0);
        // layer 1
        init_acc(acc, g_pack + OFS_BD1, j0);
        gemm_phase(acc, g_pack + OFS_DWIH1, 128, h0_s, wb, tid, r0, j0);
        gemm_phase(acc, g_pack + OFS_DWHH1, 128, h1_s, wb, tid, r0, j0);
        cell_update(acc, c1p, h1_s, r0, j0);
        // fc: out = h1 @ fcW^T + fcb ; write output + feedback
        if (tid < 2 * MT) {
            int r = tid >> 1, o = tid & 1;
            float s = fcb_s[o];
            #pragma unroll 8
            for (int k = 0; k < NH; ++k)
                s = fmaf(h1_s[k * APAD + r], fcw_s[o * NH + k], s);
            out[((size_t)(b0 + r) * tl + t) * NOUT + o] = s;
            x_s[o * APAD + r] = s;
        }
        __syncthreads();
    }
}

// ---------------- launch ----------------
extern "C" void kernel_launch(void* const* d_in, const int* in_sizes, int n_in,
                              void* d_out, int out_size)
{
    (void)in_sizes; (void)n_in; (void)out_size;
    const float* x      = (const float*)d_in[0];
    const int*   tl     = (const int*)  d_in[1];
    const float* eW_ih0 = (const float*)d_in[2];
    const float* eW_hh0 = (const float*)d_in[3];
    const float* eb_ih0 = (const float*)d_in[4];
    const float* eb_hh0 = (const float*)d_in[5];
    const float* eW_ih1 = (const float*)d_in[6];
    const float* eW_hh1 = (const float*)d_in[7];
    const float* eb_ih1 = (const float*)d_in[8];
    const float* eb_hh1 = (const float*)d_in[9];
    const float* dW_ih0 = (const float*)d_in[10];
    const float* dW_hh0 = (const float*)d_in[11];
    const float* db_ih0 = (const float*)d_in[12];
    const float* db_hh0 = (const float*)d_in[13];
    const float* dW_ih1 = (const float*)d_in[14];
    const float* dW_hh1 = (const float*)d_in[15];
    const float* db_ih1 = (const float*)d_in[16];
    const float* db_hh1 = (const float*)d_in[17];
    const float* fcW    = (const float*)d_in[18];
    const float* fcb    = (const float*)d_in[19];

    cudaFuncSetAttribute(lstm_kernel, cudaFuncAttributeMaxDynamicSharedMemorySize, SH_BYTES);

    pack_kernel<<<12, 256>>>(eW_ih0, eW_hh0, eb_ih0, eb_hh0,
                             eW_ih1, eW_hh1, eb_ih1, eb_hh1,
                             dW_ih0, dW_hh0, db_ih0, db_hh0,
                             dW_ih1, dW_hh1, db_ih1, db_hh1);

    lstm_kernel<<<NB / MT, NTHR, SH_BYTES>>>(x, tl, fcW, fcb, (float*)d_out);
}